// round 15
// baseline (speedup 1.0000x reference)
#include <cuda_runtime.h>
#include <math.h>

#define EPS 1e-8f
#define L_FRAMES 384
#define NPTS 543
#define NLM 62
#define OUTF 744      // 5*124 + 2*62
#define ROWF (NPTS*3) // 1629
#define FPB 16        // frames per main block (confirmed optimum)
#define SF (FPB + 2)  // staged frames (halo of 2)
#define MBLK (L_FRAMES / FPB)  // 24 main blocks per batch
#define NSEG 8
#define FSEG (L_FRAMES / NSEG) // 48
#define FPT (FSEG / 4)         // 12 frames per gather thread
#define FH (FPT / 2)           // 6 frames per load wave
#define MAXB 256

__constant__ int c_lm[NLM] = {
    33,133,362,263,61,291,199,419,17,84,17,314,405,320,307,375,321,308,324,318,
    501,502,503,504,505,506,507,508,509,510,511,512,513,514,515,516,517,518,519,520,521,
    522,523,524,525,526,527,528,529,530,531,532,533,534,535,536,537,538,539,540,541,542
};

// partial sums: [b][seg][6] = sx, sy, qx, qy, nose_x, nose_y
__device__ float g_part[1024 * NSEG * 6];
// compact gathered landmarks (raw, NaN preserved): [b][l][n] -> (x,y)
__device__ __align__(16) float2 g_comp[MAXB * L_FRAMES * NLM];
// producer-consumer handshake (self-resetting each replay; zero-init at load)
__device__ int g_ready[1024];
__device__ int g_done[1024];

__device__ __forceinline__ float nan0(float v) { return (v != v) ? 0.0f : v; }

// ---------------------------------------------------------------------------
// Fused kernel. bid < B*NSEG: gather role (batch-major). Else: main role.
// ---------------------------------------------------------------------------
__global__ __launch_bounds__(256, 8) void fused_kernel(const float* __restrict__ x,
                                                       float* __restrict__ out, int B) {
    const int bid = blockIdx.x;
    const int n_gather = B * NSEG;
    const int tid = threadIdx.x;

    __shared__ __align__(16) float2 s[SF][NLM];   // main staging (gather reuses head)
    __shared__ float sh6[6];

    if (bid < n_gather) {
        // ============================ GATHER ================================
        const int b   = bid / NSEG;
        const int seg = bid - b * NSEG;
        const int n   = tid & 63;      // landmark lane
        const int fy  = tid >> 6;      // 0..3 frame phase
        const int l0  = seg * FSEG;

        float sx = 0.f, sy = 0.f, qx = 0.f, qy = 0.f, nx = 0.f, ny = 0.f;

        if (n < NLM) {
            const float* p0 = x + (size_t)b * L_FRAMES * ROWF
                                + (size_t)(l0 + fy) * ROWF + c_lm[n] * 3;
            float2* cp = g_comp + ((size_t)b * L_FRAMES + (l0 + fy)) * NLM + n;
            const bool is_nose = (n == 8);   // c_lm[8] == 17

            #pragma unroll
            for (int h = 0; h < 2; h++) {    // two waves of 6 frames
                float vx[FH], vy[FH];
                #pragma unroll
                for (int j = 0; j < FH; j++) {
                    const size_t off = (size_t)(h * FH + j) * (4 * ROWF);
                    vx[j] = __ldcs(p0 + off);
                    vy[j] = __ldcs(p0 + off + 1);
                }
                #pragma unroll
                for (int j = 0; j < FH; j++) {
                    cp[(size_t)(h * FH + j) * (4 * NLM)] = make_float2(vx[j], vy[j]);
                    const float cx = (vx[j] != vx[j]) ? 0.0f : vx[j];
                    const float cy = (vy[j] != vy[j]) ? 0.0f : vy[j];
                    sx += cx; sy += cy;
                    qx = fmaf(cx, cx, qx); qy = fmaf(cy, cy, qy);
                    if (is_nose) {
                        nx += (vx[j] != vx[j]) ? 0.5f : vx[j];
                        ny += (vy[j] != vy[j]) ? 0.5f : vy[j];
                    }
                }
            }
        }

        #pragma unroll
        for (int off = 16; off; off >>= 1) {
            sx += __shfl_down_sync(0xffffffffu, sx, off);
            sy += __shfl_down_sync(0xffffffffu, sy, off);
            qx += __shfl_down_sync(0xffffffffu, qx, off);
            qy += __shfl_down_sync(0xffffffffu, qy, off);
            nx += __shfl_down_sync(0xffffffffu, nx, off);
            ny += __shfl_down_sync(0xffffffffu, ny, off);
        }
        float (*shr)[8] = reinterpret_cast<float (*)[8]>(&s[0][0]);
        const int wid = tid >> 5, lane = tid & 31;
        if (lane == 0) {
            shr[0][wid] = sx; shr[1][wid] = sy;
            shr[2][wid] = qx; shr[3][wid] = qy;
            shr[4][wid] = nx; shr[5][wid] = ny;
        }
        __syncthreads();
        if (tid < 6) {
            float v = 0.f;
            #pragma unroll
            for (int w = 0; w < 8; w++) v += shr[tid][w];
            g_part[((size_t)b * NSEG + seg) * 6 + tid] = v;
        }
        __syncthreads();
        if (tid == 0) {
            __threadfence();
            atomicAdd(&g_ready[b], 1);
        }
    } else {
        // ============================= MAIN =================================
        const int mbid = bid - n_gather;
        const int b  = mbid / MBLK;
        const int lb = mbid - b * MBLK;
        const int l_base = lb * FPB;

        // acquire
        if (tid == 0) {
            while (atomicAdd(&g_ready[b], 0) < NSEG) __nanosleep(128);
            __threadfence();
        }
        __syncthreads();

        // stage raw compact points (vectorized contiguous copy for interior
        // chunks; clamped per-element path only for the last chunk)
        const float2* cb = g_comp + (size_t)b * L_FRAMES * NLM;
        if (lb != MBLK - 1) {
            const float4* src = reinterpret_cast<const float4*>(cb + (size_t)l_base * NLM);
            float4* dst = reinterpret_cast<float4*>(&s[0][0]);
            #pragma unroll
            for (int i = tid; i < (SF * NLM) / 2; i += 256)   // 558 float4
                dst[i] = src[i];
        } else {
            for (int i = tid; i < SF * NLM; i += 256) {
                const int f = i / NLM;
                const int n = i - f * NLM;
                const int fr = min(l_base + f, L_FRAMES - 1);
                s[f][n] = cb[(size_t)fr * NLM + n];
            }
        }
        if (tid < 6) {
            float v = 0.f;
            #pragma unroll
            for (int sg = 0; sg < NSEG; sg++) v += g_part[((size_t)b * NSEG + sg) * 6 + tid];
            sh6[tid] = v;
        }
        __syncthreads();

        const float fM = (float)(L_FRAMES * NLM);
        const float mx = sh6[4] / (float)L_FRAMES;
        const float my = sh6[5] / (float)L_FRAMES;
        float varx = (sh6[2] - sh6[0] * sh6[0] / fM) / (fM - 1.0f);
        float vary = (sh6[3] - sh6[1] * sh6[1] / fM) / (fM - 1.0f);
        const float rx = 1.0f / (sqrtf(fmaxf(varx, 0.0f)) + EPS);
        const float ry = 1.0f / (sqrtf(fmaxf(vary, 0.0f)) + EPS);

        const int n  = tid & 63;
        const int ty = tid >> 6;       // 0..3
        if (n < NLM) {
            const bool hn = (n + 1 < NLM);
            const int np = hn ? (n + 1) : n;

            for (int k = 0; k < FPB / 4; k++) {
                const int ly = ty + k * 4;
                const int l = l_base + ly;
                const bool h1 = (l + 1 < L_FRAMES);
                const bool h2 = (l + 2 < L_FRAMES);

                const float2 p0 = s[ly][n];
                const float2 p1 = s[ly + 1][n];
                const float2 p2 = s[ly + 2][n];
                const float2 pn = s[ly][np];

                const float x0 = (p0.x - mx) * rx, y0 = (p0.y - my) * ry;
                float dx_ = 0.f, dy_ = 0.f;
                if (h1) { dx_ = (p1.x - p0.x) * rx; dy_ = (p1.y - p0.y) * ry; }
                float d2x = 0.f, d2y = 0.f;
                if (h2) { d2x = (p2.x - p0.x) * rx; d2y = (p2.y - p0.y) * ry; }
                float rlx = 0.f, rly = 0.f;
                if (h1 && hn) { rlx = (p1.x - pn.x) * rx; rly = (p1.y - pn.y) * ry; }
                float tc = 0.f;
                if (h2) {
                    const float ux = dx_, uy = dy_;
                    const float vx = (p2.x - p1.x) * rx, vy = (p2.y - p1.y) * ry;
                    const float nu = fmaxf(sqrtf(ux * ux + uy * uy), EPS);
                    const float nv = fmaxf(sqrtf(vx * vx + vy * vy), EPS);
                    tc = (ux * vx + uy * vy) / (nu * nv);
                }
                const float mag = sqrtf(dx_ * dx_ + dy_ * dy_);
                const float dir = atan2f(dy_, dx_);

                float* o = out + ((size_t)b * L_FRAMES + l) * OUTF;

                float2 v;
                v.x = nan0(x0);  v.y = nan0(y0);
                reinterpret_cast<float2*>(o)[n] = v;                   // [0:124)
                v.x = nan0(dx_); v.y = nan0(dy_);
                reinterpret_cast<float2*>(o + 124)[n] = v;             // [124:248)
                v.x = nan0(d2x); v.y = nan0(d2y);
                reinterpret_cast<float2*>(o + 248)[n] = v;             // [248:372)
                v.x = nan0(rlx); v.y = nan0(rly);
                reinterpret_cast<float2*>(o + 372)[n] = v;             // [372:496)
                const float tcz = nan0(tc);
                v.x = tcz; v.y = tcz;
                reinterpret_cast<float2*>(o + 496)[n] = v;             // [496:620)
                o[620 + n] = nan0(mag);                                // [620:682)
                o[682 + n] = nan0(dir);                                // [682:744)
            }
        }

        // self-reset for next graph replay: last main block of batch b
        __syncthreads();
        if (tid == 0) {
            const int old = atomicAdd(&g_done[b], 1);
            if (old == MBLK - 1) {
                g_done[b] = 0;
                g_ready[b] = 0;
            }
        }
    }
}

// ---------------------------------------------------------------------------
extern "C" void kernel_launch(void* const* d_in, const int* in_sizes, int n_in,
                              void* d_out, int out_size) {
    const float* x = (const float*)d_in[0];
    float* out = (float*)d_out;

    const int B = in_sizes[0] / (L_FRAMES * ROWF);

    const int n_blocks = B * NSEG + B * MBLK;
    fused_kernel<<<n_blocks, 256>>>(x, out, B);
}

// round 16
// speedup vs baseline: 1.0912x; 1.0912x over previous
#include <cuda_runtime.h>
#include <math.h>

#define EPS 1e-8f
#define L_FRAMES 384
#define NPTS 543
#define NLM 62
#define OUTF 744      // 5*124 + 2*62
#define ROWF (NPTS*3) // 1629
#define FPB 16        // frames per main block (confirmed optimum)
#define SF (FPB + 2)  // staged frames (halo of 2)
#define MBLK (L_FRAMES / FPB)  // 24 main blocks per batch
#define NSEG 8
#define FSEG (L_FRAMES / NSEG) // 48
#define FPT (FSEG / 4)         // 12 frames per gather thread
#define FH (FPT / 2)           // 6 frames per load wave
#define MAXB 256

__constant__ int c_lm[NLM] = {
    33,133,362,263,61,291,199,419,17,84,17,314,405,320,307,375,321,308,324,318,
    501,502,503,504,505,506,507,508,509,510,511,512,513,514,515,516,517,518,519,520,521,
    522,523,524,525,526,527,528,529,530,531,532,533,534,535,536,537,538,539,540,541,542
};

// partial sums: [b][seg][6] = sx, sy, qx, qy, nose_x, nose_y
__device__ float g_part[1024 * NSEG * 6];
// compact gathered landmarks (raw, NaN preserved): [b][l][n] -> (x,y)
__device__ __align__(16) float2 g_comp[MAXB * L_FRAMES * NLM];
// producer-consumer handshake (self-resetting each replay; zero-init at load)
__device__ int g_ready[1024];
__device__ int g_done[1024];

__device__ __forceinline__ float nan0(float v) { return (v != v) ? 0.0f : v; }

// ---------------------------------------------------------------------------
// Fused kernel. bid < B*NSEG: gather role (batch-major). Else: main role.
// ---------------------------------------------------------------------------
__global__ __launch_bounds__(256, 8) void fused_kernel(const float* __restrict__ x,
                                                       float* __restrict__ out, int B) {
    const int bid = blockIdx.x;
    const int n_gather = B * NSEG;
    const int tid = threadIdx.x;

    __shared__ __align__(16) float2 s[SF][NLM];   // main staging (gather reuses head)
    __shared__ float sh6[6];

    if (bid < n_gather) {
        // ============================ GATHER ================================
        const int b   = bid / NSEG;
        const int seg = bid - b * NSEG;
        const int n   = tid & 63;      // landmark lane
        const int fy  = tid >> 6;      // 0..3 frame phase
        const int l0  = seg * FSEG;

        float sx = 0.f, sy = 0.f, qx = 0.f, qy = 0.f, nx = 0.f, ny = 0.f;

        if (n < NLM) {
            const float* p0 = x + (size_t)b * L_FRAMES * ROWF
                                + (size_t)(l0 + fy) * ROWF + c_lm[n] * 3;
            float2* cp = g_comp + ((size_t)b * L_FRAMES + (l0 + fy)) * NLM + n;
            const bool is_nose = (n == 8);   // c_lm[8] == 17

            #pragma unroll
            for (int h = 0; h < 2; h++) {    // two waves of 6 frames
                float vx[FH], vy[FH];
                #pragma unroll
                for (int j = 0; j < FH; j++) {
                    const size_t off = (size_t)(h * FH + j) * (4 * ROWF);
                    vx[j] = __ldcs(p0 + off);
                    vy[j] = __ldcs(p0 + off + 1);
                }
                #pragma unroll
                for (int j = 0; j < FH; j++) {
                    cp[(size_t)(h * FH + j) * (4 * NLM)] = make_float2(vx[j], vy[j]);
                    const float cx = (vx[j] != vx[j]) ? 0.0f : vx[j];
                    const float cy = (vy[j] != vy[j]) ? 0.0f : vy[j];
                    sx += cx; sy += cy;
                    qx = fmaf(cx, cx, qx); qy = fmaf(cy, cy, qy);
                    if (is_nose) {
                        nx += (vx[j] != vx[j]) ? 0.5f : vx[j];
                        ny += (vy[j] != vy[j]) ? 0.5f : vy[j];
                    }
                }
            }
        }

        #pragma unroll
        for (int off = 16; off; off >>= 1) {
            sx += __shfl_down_sync(0xffffffffu, sx, off);
            sy += __shfl_down_sync(0xffffffffu, sy, off);
            qx += __shfl_down_sync(0xffffffffu, qx, off);
            qy += __shfl_down_sync(0xffffffffu, qy, off);
            nx += __shfl_down_sync(0xffffffffu, nx, off);
            ny += __shfl_down_sync(0xffffffffu, ny, off);
        }
        float (*shr)[8] = reinterpret_cast<float (*)[8]>(&s[0][0]);
        const int wid = tid >> 5, lane = tid & 31;
        if (lane == 0) {
            shr[0][wid] = sx; shr[1][wid] = sy;
            shr[2][wid] = qx; shr[3][wid] = qy;
            shr[4][wid] = nx; shr[5][wid] = ny;
        }
        __syncthreads();
        if (tid < 6) {
            float v = 0.f;
            #pragma unroll
            for (int w = 0; w < 8; w++) v += shr[tid][w];
            g_part[((size_t)b * NSEG + seg) * 6 + tid] = v;
        }
        __syncthreads();
        if (tid == 0) {
            __threadfence();
            atomicAdd(&g_ready[b], 1);
        }
    } else {
        // ============================= MAIN =================================
        const int mbid = bid - n_gather;
        const int b  = mbid / MBLK;
        const int lb = mbid - b * MBLK;
        const int l_base = lb * FPB;

        // acquire
        if (tid == 0) {
            while (atomicAdd(&g_ready[b], 0) < NSEG) __nanosleep(128);
            __threadfence();
        }
        __syncthreads();

        // stage raw compact points (vectorized contiguous copy for interior
        // chunks; clamped per-element path only for the last chunk)
        const float2* cb = g_comp + (size_t)b * L_FRAMES * NLM;
        if (lb != MBLK - 1) {
            const float4* src = reinterpret_cast<const float4*>(cb + (size_t)l_base * NLM);
            float4* dst = reinterpret_cast<float4*>(&s[0][0]);
            #pragma unroll
            for (int i = tid; i < (SF * NLM) / 2; i += 256)   // 558 float4
                dst[i] = src[i];
        } else {
            for (int i = tid; i < SF * NLM; i += 256) {
                const int f = i / NLM;
                const int n = i - f * NLM;
                const int fr = min(l_base + f, L_FRAMES - 1);
                s[f][n] = cb[(size_t)fr * NLM + n];
            }
        }
        if (tid < 6) {
            float v = 0.f;
            #pragma unroll
            for (int sg = 0; sg < NSEG; sg++) v += g_part[((size_t)b * NSEG + sg) * 6 + tid];
            sh6[tid] = v;
        }
        __syncthreads();

        const float fM = (float)(L_FRAMES * NLM);
        const float mx = sh6[4] / (float)L_FRAMES;
        const float my = sh6[5] / (float)L_FRAMES;
        float varx = (sh6[2] - sh6[0] * sh6[0] / fM) / (fM - 1.0f);
        float vary = (sh6[3] - sh6[1] * sh6[1] / fM) / (fM - 1.0f);
        const float rx = 1.0f / (sqrtf(fmaxf(varx, 0.0f)) + EPS);
        const float ry = 1.0f / (sqrtf(fmaxf(vary, 0.0f)) + EPS);

        const int n  = tid & 63;
        const int ty = tid >> 6;       // 0..3
        if (n < NLM) {
            const bool hn = (n + 1 < NLM);
            const int np = hn ? (n + 1) : n;

            for (int k = 0; k < FPB / 4; k++) {
                const int ly = ty + k * 4;
                const int l = l_base + ly;
                const bool h1 = (l + 1 < L_FRAMES);
                const bool h2 = (l + 2 < L_FRAMES);

                const float2 p0 = s[ly][n];
                const float2 p1 = s[ly + 1][n];
                const float2 p2 = s[ly + 2][n];
                const float2 pn = s[ly][np];

                const float x0 = (p0.x - mx) * rx, y0 = (p0.y - my) * ry;
                float dx_ = 0.f, dy_ = 0.f;
                if (h1) { dx_ = (p1.x - p0.x) * rx; dy_ = (p1.y - p0.y) * ry; }
                float d2x = 0.f, d2y = 0.f;
                if (h2) { d2x = (p2.x - p0.x) * rx; d2y = (p2.y - p0.y) * ry; }
                float rlx = 0.f, rly = 0.f;
                if (h1 && hn) { rlx = (p1.x - pn.x) * rx; rly = (p1.y - pn.y) * ry; }
                float tc = 0.f;
                if (h2) {
                    const float ux = dx_, uy = dy_;
                    const float vx = (p2.x - p1.x) * rx, vy = (p2.y - p1.y) * ry;
                    const float nu = fmaxf(sqrtf(ux * ux + uy * uy), EPS);
                    const float nv = fmaxf(sqrtf(vx * vx + vy * vy), EPS);
                    tc = (ux * vx + uy * vy) / (nu * nv);
                }
                const float mag = sqrtf(dx_ * dx_ + dy_ * dy_);
                const float dir = atan2f(dy_, dx_);

                float* o = out + ((size_t)b * L_FRAMES + l) * OUTF;

                float2 v;
                v.x = nan0(x0);  v.y = nan0(y0);
                __stcs(reinterpret_cast<float2*>(o) + n, v);           // [0:124)
                v.x = nan0(dx_); v.y = nan0(dy_);
                __stcs(reinterpret_cast<float2*>(o + 124) + n, v);     // [124:248)
                v.x = nan0(d2x); v.y = nan0(d2y);
                __stcs(reinterpret_cast<float2*>(o + 248) + n, v);     // [248:372)
                v.x = nan0(rlx); v.y = nan0(rly);
                __stcs(reinterpret_cast<float2*>(o + 372) + n, v);     // [372:496)
                const float tcz = nan0(tc);
                v.x = tcz; v.y = tcz;
                __stcs(reinterpret_cast<float2*>(o + 496) + n, v);     // [496:620)
                __stcs(o + 620 + n, nan0(mag));                        // [620:682)
                __stcs(o + 682 + n, nan0(dir));                        // [682:744)
            }
        }

        // self-reset for next graph replay: last main block of batch b
        __syncthreads();
        if (tid == 0) {
            const int old = atomicAdd(&g_done[b], 1);
            if (old == MBLK - 1) {
                g_done[b] = 0;
                g_ready[b] = 0;
            }
        }
    }
}

// ---------------------------------------------------------------------------
extern "C" void kernel_launch(void* const* d_in, const int* in_sizes, int n_in,
                              void* d_out, int out_size) {
    const float* x = (const float*)d_in[0];
    float* out = (float*)d_out;

    const int B = in_sizes[0] / (L_FRAMES * ROWF);

    const int n_blocks = B * NSEG + B * MBLK;
    fused_kernel<<<n_blocks, 256>>>(x, out, B);
}

// round 17
// speedup vs baseline: 1.1121x; 1.0192x over previous
#include <cuda_runtime.h>
#include <math.h>

#define EPS 1e-8f
#define L_FRAMES 384
#define NPTS 543
#define NLM 62
#define OUTF 744      // 5*124 + 2*62
#define ROWF (NPTS*3) // 1629
#define FPB 16        // frames per main block (confirmed optimum)
#define SF (FPB + 2)  // staged frames (halo of 2)
#define MBLK (L_FRAMES / FPB)  // 24 main blocks per batch
#define NSEG 16                // probe: 16 gather segments (was 8)
#define FSEG (L_FRAMES / NSEG) // 24 frames per gather segment
#define FPT (FSEG / 4)         // 6 frames per gather thread (12 loads, one wave)
#define MAXB 256

__constant__ int c_lm[NLM] = {
    33,133,362,263,61,291,199,419,17,84,17,314,405,320,307,375,321,308,324,318,
    501,502,503,504,505,506,507,508,509,510,511,512,513,514,515,516,517,518,519,520,521,
    522,523,524,525,526,527,528,529,530,531,532,533,534,535,536,537,538,539,540,541,542
};

// partial sums: [b][seg][6] = sx, sy, qx, qy, nose_x, nose_y
__device__ float g_part[1024 * NSEG * 6];
// compact gathered landmarks (raw, NaN preserved): [b][l][n] -> (x,y)
__device__ __align__(16) float2 g_comp[MAXB * L_FRAMES * NLM];
// producer-consumer handshake (self-resetting each replay; zero-init at load)
__device__ int g_ready[1024];
__device__ int g_done[1024];

__device__ __forceinline__ float nan0(float v) { return (v != v) ? 0.0f : v; }

// ---------------------------------------------------------------------------
// Fused kernel. bid < B*NSEG: gather role (batch-major). Else: main role.
// ---------------------------------------------------------------------------
__global__ __launch_bounds__(256, 8) void fused_kernel(const float* __restrict__ x,
                                                       float* __restrict__ out, int B) {
    const int bid = blockIdx.x;
    const int n_gather = B * NSEG;
    const int tid = threadIdx.x;

    __shared__ __align__(16) float2 s[SF][NLM];   // main staging (gather reuses head)
    __shared__ float sh6[6];

    if (bid < n_gather) {
        // ============================ GATHER ================================
        const int b   = bid / NSEG;
        const int seg = bid - b * NSEG;
        const int n   = tid & 63;      // landmark lane
        const int fy  = tid >> 6;      // 0..3 frame phase
        const int l0  = seg * FSEG;

        float sx = 0.f, sy = 0.f, qx = 0.f, qy = 0.f, nx = 0.f, ny = 0.f;

        if (n < NLM) {
            const float* p0 = x + (size_t)b * L_FRAMES * ROWF
                                + (size_t)(l0 + fy) * ROWF + c_lm[n] * 3;
            float2* cp = g_comp + ((size_t)b * L_FRAMES + (l0 + fy)) * NLM + n;
            const bool is_nose = (n == 8);   // c_lm[8] == 17

            // single wave: all 12 loads outstanding
            float vx[FPT], vy[FPT];
            #pragma unroll
            for (int j = 0; j < FPT; j++) {
                const size_t off = (size_t)j * (4 * ROWF);
                vx[j] = __ldcs(p0 + off);
                vy[j] = __ldcs(p0 + off + 1);
            }
            #pragma unroll
            for (int j = 0; j < FPT; j++) {
                cp[(size_t)j * (4 * NLM)] = make_float2(vx[j], vy[j]);
                const float cx = (vx[j] != vx[j]) ? 0.0f : vx[j];
                const float cy = (vy[j] != vy[j]) ? 0.0f : vy[j];
                sx += cx; sy += cy;
                qx = fmaf(cx, cx, qx); qy = fmaf(cy, cy, qy);
                if (is_nose) {
                    nx += (vx[j] != vx[j]) ? 0.5f : vx[j];
                    ny += (vy[j] != vy[j]) ? 0.5f : vy[j];
                }
            }
        }

        #pragma unroll
        for (int off = 16; off; off >>= 1) {
            sx += __shfl_down_sync(0xffffffffu, sx, off);
            sy += __shfl_down_sync(0xffffffffu, sy, off);
            qx += __shfl_down_sync(0xffffffffu, qx, off);
            qy += __shfl_down_sync(0xffffffffu, qy, off);
            nx += __shfl_down_sync(0xffffffffu, nx, off);
            ny += __shfl_down_sync(0xffffffffu, ny, off);
        }
        float (*shr)[8] = reinterpret_cast<float (*)[8]>(&s[0][0]);
        const int wid = tid >> 5, lane = tid & 31;
        if (lane == 0) {
            shr[0][wid] = sx; shr[1][wid] = sy;
            shr[2][wid] = qx; shr[3][wid] = qy;
            shr[4][wid] = nx; shr[5][wid] = ny;
        }
        __syncthreads();
        if (tid < 6) {
            float v = 0.f;
            #pragma unroll
            for (int w = 0; w < 8; w++) v += shr[tid][w];
            g_part[((size_t)b * NSEG + seg) * 6 + tid] = v;
        }
        __syncthreads();
        if (tid == 0) {
            __threadfence();
            atomicAdd(&g_ready[b], 1);
        }
    } else {
        // ============================= MAIN =================================
        const int mbid = bid - n_gather;
        const int b  = mbid / MBLK;
        const int lb = mbid - b * MBLK;
        const int l_base = lb * FPB;

        // acquire
        if (tid == 0) {
            while (atomicAdd(&g_ready[b], 0) < NSEG) __nanosleep(128);
            __threadfence();
        }
        __syncthreads();

        // stage raw compact points (vectorized contiguous copy for interior
        // chunks; clamped per-element path only for the last chunk)
        const float2* cb = g_comp + (size_t)b * L_FRAMES * NLM;
        if (lb != MBLK - 1) {
            const float4* src = reinterpret_cast<const float4*>(cb + (size_t)l_base * NLM);
            float4* dst = reinterpret_cast<float4*>(&s[0][0]);
            #pragma unroll
            for (int i = tid; i < (SF * NLM) / 2; i += 256)   // 558 float4
                dst[i] = src[i];
        } else {
            for (int i = tid; i < SF * NLM; i += 256) {
                const int f = i / NLM;
                const int n = i - f * NLM;
                const int fr = min(l_base + f, L_FRAMES - 1);
                s[f][n] = cb[(size_t)fr * NLM + n];
            }
        }
        if (tid < 6) {
            float v = 0.f;
            #pragma unroll
            for (int sg = 0; sg < NSEG; sg++) v += g_part[((size_t)b * NSEG + sg) * 6 + tid];
            sh6[tid] = v;
        }
        __syncthreads();

        const float fM = (float)(L_FRAMES * NLM);
        const float mx = sh6[4] / (float)L_FRAMES;
        const float my = sh6[5] / (float)L_FRAMES;
        float varx = (sh6[2] - sh6[0] * sh6[0] / fM) / (fM - 1.0f);
        float vary = (sh6[3] - sh6[1] * sh6[1] / fM) / (fM - 1.0f);
        const float rx = 1.0f / (sqrtf(fmaxf(varx, 0.0f)) + EPS);
        const float ry = 1.0f / (sqrtf(fmaxf(vary, 0.0f)) + EPS);

        const int n  = tid & 63;
        const int ty = tid >> 6;       // 0..3
        if (n < NLM) {
            const bool hn = (n + 1 < NLM);
            const int np = hn ? (n + 1) : n;

            for (int k = 0; k < FPB / 4; k++) {
                const int ly = ty + k * 4;
                const int l = l_base + ly;
                const bool h1 = (l + 1 < L_FRAMES);
                const bool h2 = (l + 2 < L_FRAMES);

                const float2 p0 = s[ly][n];
                const float2 p1 = s[ly + 1][n];
                const float2 p2 = s[ly + 2][n];
                const float2 pn = s[ly][np];

                const float x0 = (p0.x - mx) * rx, y0 = (p0.y - my) * ry;
                float dx_ = 0.f, dy_ = 0.f;
                if (h1) { dx_ = (p1.x - p0.x) * rx; dy_ = (p1.y - p0.y) * ry; }
                float d2x = 0.f, d2y = 0.f;
                if (h2) { d2x = (p2.x - p0.x) * rx; d2y = (p2.y - p0.y) * ry; }
                float rlx = 0.f, rly = 0.f;
                if (h1 && hn) { rlx = (p1.x - pn.x) * rx; rly = (p1.y - pn.y) * ry; }
                float tc = 0.f;
                if (h2) {
                    const float ux = dx_, uy = dy_;
                    const float vx = (p2.x - p1.x) * rx, vy = (p2.y - p1.y) * ry;
                    const float nu = fmaxf(sqrtf(ux * ux + uy * uy), EPS);
                    const float nv = fmaxf(sqrtf(vx * vx + vy * vy), EPS);
                    tc = (ux * vx + uy * vy) / (nu * nv);
                }
                const float mag = sqrtf(dx_ * dx_ + dy_ * dy_);
                const float dir = atan2f(dy_, dx_);

                float* o = out + ((size_t)b * L_FRAMES + l) * OUTF;

                float2 v;
                v.x = nan0(x0);  v.y = nan0(y0);
                __stcs(reinterpret_cast<float2*>(o) + n, v);           // [0:124)
                v.x = nan0(dx_); v.y = nan0(dy_);
                __stcs(reinterpret_cast<float2*>(o + 124) + n, v);     // [124:248)
                v.x = nan0(d2x); v.y = nan0(d2y);
                __stcs(reinterpret_cast<float2*>(o + 248) + n, v);     // [248:372)
                v.x = nan0(rlx); v.y = nan0(rly);
                __stcs(reinterpret_cast<float2*>(o + 372) + n, v);     // [372:496)
                const float tcz = nan0(tc);
                v.x = tcz; v.y = tcz;
                __stcs(reinterpret_cast<float2*>(o + 496) + n, v);     // [496:620)
                __stcs(o + 620 + n, nan0(mag));                        // [620:682)
                __stcs(o + 682 + n, nan0(dir));                        // [682:744)
            }
        }

        // self-reset for next graph replay: last main block of batch b
        __syncthreads();
        if (tid == 0) {
            const int old = atomicAdd(&g_done[b], 1);
            if (old == MBLK - 1) {
                g_done[b] = 0;
                g_ready[b] = 0;
            }
        }
    }
}

// ---------------------------------------------------------------------------
extern "C" void kernel_launch(void* const* d_in, const int* in_sizes, int n_in,
                              void* d_out, int out_size) {
    const float* x = (const float*)d_in[0];
    float* out = (float*)d_out;

    const int B = in_sizes[0] / (L_FRAMES * ROWF);

    const int n_blocks = B * NSEG + B * MBLK;
    fused_kernel<<<n_blocks, 256>>>(x, out, B);
}